// round 1
// baseline (speedup 1.0000x reference)
#include <cuda_runtime.h>

#define NN   50000
#define DD   128
#define NV4  (DD / 4)          // 32 float4 per row
#define NNZ_CAP 800000

// ---- static scratch (allocation-free rule: __device__ globals) ----
__device__ float g_bufA[NN * DD];
__device__ float g_bufB[NN * DD];
__device__ float g_bufC[NN * DD];
__device__ int   g_cnt[NN];
__device__ int   g_rptr[NN + 1];
__device__ int   g_cursor[NN];
__device__ int2  g_edges[NNZ_CAP];   // {col, val-as-int}

// ---------------- CSR build ----------------
__global__ void hist_kernel(const int* __restrict__ rows, int nnz) {
    int i = blockIdx.x * blockDim.x + threadIdx.x;
    if (i < nnz) atomicAdd(&g_cnt[rows[i]], 1);
}

__global__ void scan_kernel(int nnz) {
    __shared__ int sh[1024];
    const int t  = threadIdx.x;
    const int CH = (NN + 1023) / 1024;
    const int base = t * CH;

    int sum = 0;
    #pragma unroll 4
    for (int i = 0; i < CH; i++) {
        int idx = base + i;
        if (idx < NN) sum += g_cnt[idx];
    }
    sh[t] = sum;
    __syncthreads();

    // Hillis-Steele inclusive scan over 1024 partials
    for (int d = 1; d < 1024; d <<= 1) {
        int v = (t >= d) ? sh[t - d] : 0;
        __syncthreads();
        sh[t] += v;
        __syncthreads();
    }

    int off = sh[t] - sum;   // exclusive prefix for this chunk
    for (int i = 0; i < CH; i++) {
        int idx = base + i;
        if (idx < NN) {
            g_rptr[idx]   = off;
            g_cursor[idx] = off;
            off += g_cnt[idx];
        }
    }
    if (t == 1023) g_rptr[NN] = nnz;
}

__global__ void scatter_kernel(const int* __restrict__ rows,
                               const int* __restrict__ cols,
                               const float* __restrict__ vals, int nnz) {
    int i = blockIdx.x * blockDim.x + threadIdx.x;
    if (i < nnz) {
        int r = rows[i];
        int p = atomicAdd(&g_cursor[r], 1);
        g_edges[p] = make_int2(cols[i], __float_as_int(vals[i]));
    }
}

// ---------------- fused Chebyshev kernels ----------------
// warp per row; lane owns one float4 (4 feature columns)

__device__ __forceinline__ float4 spmm_row(const float4* __restrict__ Tc4,
                                           int s, int e, int lane) {
    float4 a = make_float4(0.f, 0.f, 0.f, 0.f);
    int i = s;
    // unroll-by-2 to raise MLP on the L2 gathers
    for (; i + 1 < e; i += 2) {
        int2 e0 = __ldg(&g_edges[i]);
        int2 e1 = __ldg(&g_edges[i + 1]);
        float4 x0 = __ldg(&Tc4[e0.x * NV4 + lane]);
        float4 x1 = __ldg(&Tc4[e1.x * NV4 + lane]);
        float v0 = __int_as_float(e0.y);
        float v1 = __int_as_float(e1.y);
        a.x += v0 * x0.x; a.y += v0 * x0.y; a.z += v0 * x0.z; a.w += v0 * x0.w;
        a.x += v1 * x1.x; a.y += v1 * x1.y; a.z += v1 * x1.z; a.w += v1 * x1.w;
    }
    if (i < e) {
        int2 e0 = __ldg(&g_edges[i]);
        float4 x0 = __ldg(&Tc4[e0.x * NV4 + lane]);
        float v0 = __int_as_float(e0.y);
        a.x += v0 * x0.x; a.y += v0 * x0.y; a.z += v0 * x0.z; a.w += v0 * x0.w;
    }
    return a;
}

// T1 = L @ X ; acc = c0*X + c1*T1
__global__ void cheb_first(const float* __restrict__ X,
                           float* __restrict__ T1,
                           float* __restrict__ acc,
                           const float* __restrict__ coeffs) {
    int gw   = (blockIdx.x * blockDim.x + threadIdx.x) >> 5;
    int lane = threadIdx.x & 31;
    if (gw >= NN) return;
    int s = g_rptr[gw], e = g_rptr[gw + 1];

    const float4* Xv = (const float4*)X;
    float4 a = spmm_row(Xv, s, e, lane);

    int idx = gw * NV4 + lane;
    ((float4*)T1)[idx] = a;

    float4 x0 = __ldg(&Xv[idx]);
    float c0 = coeffs[0], c1 = coeffs[1];
    float4 o;
    o.x = c0 * x0.x + c1 * a.x;
    o.y = c0 * x0.y + c1 * a.y;
    o.z = c0 * x0.z + c1 * a.z;
    o.w = c0 * x0.w + c1 * a.w;
    ((float4*)acc)[idx] = o;
}

// Tk = 2*(L @ Tc) - Tp ; acc += ck*Tk ; Tn = Tk
__global__ void cheb_step(const float* __restrict__ Tc,
                          const float* __restrict__ Tp,
                          float* __restrict__ Tn,
                          float* __restrict__ acc,
                          const float* __restrict__ coeffs, int k) {
    int gw   = (blockIdx.x * blockDim.x + threadIdx.x) >> 5;
    int lane = threadIdx.x & 31;
    if (gw >= NN) return;
    int s = g_rptr[gw], e = g_rptr[gw + 1];

    const float4* Tc4 = (const float4*)Tc;
    float4 a = spmm_row(Tc4, s, e, lane);

    int idx = gw * NV4 + lane;
    float4 tp = __ldg(&((const float4*)Tp)[idx]);
    float4 tk;
    tk.x = 2.f * a.x - tp.x;
    tk.y = 2.f * a.y - tp.y;
    tk.z = 2.f * a.z - tp.z;
    tk.w = 2.f * a.w - tp.w;
    ((float4*)Tn)[idx] = tk;

    float ck = coeffs[k];
    float4* accv = (float4*)acc;
    float4 av = accv[idx];
    av.x += ck * tk.x;
    av.y += ck * tk.y;
    av.z += ck * tk.z;
    av.w += ck * tk.w;
    accv[idx] = av;
}

// ---------------- launch ----------------
extern "C" void kernel_launch(void* const* d_in, const int* in_sizes, int n_in,
                              void* d_out, int out_size) {
    const int*   rows   = (const int*)d_in[0];
    const int*   cols   = (const int*)d_in[1];
    const float* vals   = (const float*)d_in[2];
    const float* X      = (const float*)d_in[3];
    const float* coeffs = (const float*)d_in[4];
    const int nnz = in_sizes[0];
    const int M   = in_sizes[4];

    void* p;
    float *pA, *pB, *pC;
    int* pcnt;
    cudaGetSymbolAddress(&p, g_bufA); pA = (float*)p;
    cudaGetSymbolAddress(&p, g_bufB); pB = (float*)p;
    cudaGetSymbolAddress(&p, g_bufC); pC = (float*)p;
    cudaGetSymbolAddress(&p, g_cnt);  pcnt = (int*)p;

    // ---- CSR build (in-graph, re-done every replay) ----
    cudaMemsetAsync(pcnt, 0, NN * sizeof(int));
    hist_kernel<<<(nnz + 255) / 256, 256>>>(rows, nnz);
    scan_kernel<<<1, 1024>>>(nnz);
    scatter_kernel<<<(nnz + 255) / 256, 256>>>(rows, cols, vals, nnz);

    // ---- Chebyshev recurrence ----
    const int threads = 256;                 // 8 rows per block
    const int rowsPerBlk = threads / 32;
    const int grid = (NN + rowsPerBlk - 1) / rowsPerBlk;
    float* accp = (float*)d_out;

    cheb_first<<<grid, threads>>>(X, pA, accp, coeffs);

    const float* prev = X;
    float* curr = pA;
    float* nxt  = pB;
    float* spare = pC;

    for (int k = 2; k < M; k++) {
        cheb_step<<<grid, threads>>>(curr, prev, nxt, accp, coeffs, k);
        float* recycled = (k == 2) ? spare : (float*)prev;
        prev = curr;
        curr = nxt;
        nxt  = recycled;
    }
}